// round 8
// baseline (speedup 1.0000x reference)
#include <cuda_runtime.h>
#include <cuda_fp16.h>
#include <cstdint>

// Problem constants
#define BATCH 32
#define TT    4096
#define HH    256
#define TB    (TT * BATCH)     // 131072 rows of enc

// -------------------- scratch (static device arrays) -----------------------
__device__ float g_pre1[BATCH * HH];            // W1*hidden + bias
__device__ float g_scores[BATCH * TT];          // transposed scores [b][t]
// Pre-swizzled full B tile fp16: [256 n][256 k], 512B/row, 16B XOR swizzle
__device__ unsigned char g_bpk[131072];

// -------------------- helpers ----------------------------------------------
__device__ __forceinline__ uint32_t smem_u32(const void* p) {
    uint32_t a;
    asm("{ .reg .u64 t; cvta.to.shared.u64 t, %1; cvt.u32.u64 %0, t; }" : "=r"(a) : "l"(p));
    return a;
}
__device__ __forceinline__ void cp16(void* smem_dst, const void* gsrc) {
    unsigned s = (unsigned)__cvta_generic_to_shared(smem_dst);
    asm volatile("cp.async.cg.shared.global [%0], [%1], 16;\n" :: "r"(s), "l"(gsrc));
}
#define CP_COMMIT() asm volatile("cp.async.commit_group;\n" ::: "memory")
#define CP_WAIT0()  asm volatile("cp.async.wait_group 0;\n" ::: "memory")

__device__ __forceinline__ uint32_t pack_f16x2(float x, float y) {
    uint32_t r;
    asm("cvt.rn.f16x2.f32 %0, %1, %2;" : "=r"(r) : "f"(y), "f"(x));
    return r;
}
__device__ __forceinline__ void ldsm4(uint32_t* r, uint32_t addr) {
    asm volatile("ldmatrix.sync.aligned.m8n8.x4.shared.b16 {%0,%1,%2,%3}, [%4];"
                 : "=r"(r[0]), "=r"(r[1]), "=r"(r[2]), "=r"(r[3]) : "r"(addr));
}
__device__ __forceinline__ void mma16816(float* c, const uint32_t* a, uint32_t b0, uint32_t b1) {
    asm volatile("mma.sync.aligned.m16n8k16.row.col.f32.f16.f16.f32 "
                 "{%0,%1,%2,%3}, {%4,%5,%6,%7}, {%8,%9}, {%0,%1,%2,%3};"
                 : "+f"(c[0]), "+f"(c[1]), "+f"(c[2]), "+f"(c[3])
                 : "r"(a[0]), "r"(a[1]), "r"(a[2]), "r"(a[3]), "r"(b0), "r"(b1));
}

// ---------------------------------------------------------------------------
// Kernel 1 (fused init): blocks [0,1024) pre1, [1024,1280) bpack.
//   bpack: g_bpk[n*512 + ((k*2) ^ ((n&7)*16))] = fp16(attn_w[n*512 + 256 + k])
// ---------------------------------------------------------------------------
__global__ void init_kernel(const float* __restrict__ hidden,
                            const float* __restrict__ attn_w,
                            const float* __restrict__ attn_b) {
    if (blockIdx.x < 1024) {
        int gw   = (blockIdx.x * 256 + threadIdx.x) >> 5;   // 0..8191
        int lane = threadIdx.x & 31;
        int b = gw >> 8, h = gw & 255;
        const float4* hp = (const float4*)(hidden + (size_t)b * HH);
        const float4* wp = (const float4*)(attn_w + (size_t)h * (2 * HH));
        float4 x0 = hp[lane],      w0 = wp[lane];
        float4 x1 = hp[lane + 32], w1 = wp[lane + 32];
        float s = x0.x*w0.x + x0.y*w0.y + x0.z*w0.z + x0.w*w0.w
                + x1.x*w1.x + x1.y*w1.y + x1.z*w1.z + x1.w*w1.w;
        #pragma unroll
        for (int o = 16; o; o >>= 1) s += __shfl_xor_sync(0xffffffffu, s, o);
        if (lane == 0) g_pre1[gw] = s + attn_b[h];
    } else {
        int idx = (blockIdx.x - 1024) * 256 + threadIdx.x;  // 0..65535
        int n = idx >> 8;
        int k = idx & 255;
        float val = attn_w[(size_t)n * 512 + 256 + k];
        __half hv = __float2half_rn(val);
        uint32_t so = (uint32_t)n * 512 + (((uint32_t)k * 2) ^ ((uint32_t)(n & 7) * 16));
        *(uint16_t*)(g_bpk + so) = __half_as_ushort(hv);
    }
}

// ---------------------------------------------------------------------------
// Kernel 2: fp16 HMMA GEMM, B resident in smem, A via direct LDG frags.
// CTA: 128 rows x 256 cols, 512 thr (16 warps, wm 4 x wn 4), warp tile 32x64.
// Mainloop: 16 k16-steps, barrier-free.
// SMEM: B [256][512B] = 128KB @ 0
//       pre1s [32][257] @ 131072 (32896B), vs @ 164096, ps @ 165184
// ---------------------------------------------------------------------------
#define SMEM_PRE1 131072
#define SMEM_VS   164096
#define SMEM_PS   165184
#define SMEM_DYN  167296

__global__ __launch_bounds__(512, 1)
void energy_kernel(const float* __restrict__ enc, const float* __restrict__ v) {
    extern __shared__ __align__(1024) unsigned char smem[];
    const uint32_t sb = smem_u32(smem);
    const int tid = threadIdx.x, wid = tid >> 5, L = tid & 31;
    const int wm = wid >> 2, wn = wid & 3;
    const int r0 = blockIdx.x * 128;

    // ---- prologue: B cp.async (128KB), pre1/v smem fill ----
    #pragma unroll
    for (int st = 0; st < 16; st++) {
        int off = (tid + st * 512) * 16;
        cp16(smem + off, g_bpk + off);
    }
    CP_COMMIT();
    {
        float* pre1s = (float*)(smem + SMEM_PRE1);
        #pragma unroll
        for (int i = 0; i < 16; i++) {
            int idx = tid + i * 512;               // 0..8191
            int bb = idx >> 8, cc = idx & 255;
            pre1s[bb * 257 + cc] = g_pre1[idx];
        }
        if (tid < 256) ((float*)(smem + SMEM_VS))[tid] = v[tid];
    }

    float acc[2][8][4];
    #pragma unroll
    for (int i = 0; i < 2; i++)
        #pragma unroll
        for (int j = 0; j < 8; j++)
            #pragma unroll
            for (int q = 0; q < 4; q++) acc[i][j][q] = 0.f;

    // ---- A-frag loader: direct LDG of mma A fragment, fp32 -> fp16x2 ----
    // rows: wm*32 + mi*16 + (L>>2) (+8); cols: k0 + (L&3)*2 (+8)
    const float* abase = enc + (size_t)(r0 + wm * 32 + (L >> 2)) * HH + (L & 3) * 2;
    auto ldg_frag = [&](int mi, int k0, uint32_t* af) {
        const float* p0 = abase + mi * 16 * HH + k0;
        float2 f0 = *(const float2*)(p0);
        float2 f1 = *(const float2*)(p0 + 8 * HH);
        float2 f2 = *(const float2*)(p0 + 8);
        float2 f3 = *(const float2*)(p0 + 8 * HH + 8);
        af[0] = pack_f16x2(f0.x, f0.y);
        af[1] = pack_f16x2(f1.x, f1.y);
        af[2] = pack_f16x2(f2.x, f2.y);
        af[3] = pack_f16x2(f3.x, f3.y);
    };

    // ---- B ldsm addresses ----
    const int lrow16 = L & 15;
    const uint32_t lcol = (uint32_t)(L >> 4) * 16;
    uint32_t baddr[4];
    #pragma unroll
    for (int ni2 = 0; ni2 < 4; ni2++) {
        int brow = wn * 64 + ni2 * 16 + lrow16;
        baddr[ni2] = sb + (uint32_t)brow * 512 + (lcol ^ ((uint32_t)(brow & 7) * 16));
    }

    CP_WAIT0();
    __syncthreads();

    // ---- mainloop: 16 k-steps, one-step A prefetch, no barriers ----
    uint32_t acur[2][4], anxt[2][4];
    ldg_frag(0, 0, acur[0]);
    ldg_frag(1, 0, acur[1]);

    #pragma unroll
    for (int ks = 0; ks < 16; ks++) {
        if (ks < 15) {
            ldg_frag(0, (ks + 1) * 16, anxt[0]);
            ldg_frag(1, (ks + 1) * 16, anxt[1]);
        }
        uint32_t bf[4][4];
        const uint32_t kb = (uint32_t)ks * 32;
        #pragma unroll
        for (int ni2 = 0; ni2 < 4; ni2++)
            ldsm4(bf[ni2], baddr[ni2] ^ kb);   // kb bits 5-8 don't collide with swizzle bits 4-6? kb=ks*32: bits>=5; swizzle flips bits 4-6 -> XOR add safe only if disjoint... use + instead
        #pragma unroll
        for (int ni2 = 0; ni2 < 4; ni2++)
            #pragma unroll
            for (int mi = 0; mi < 2; mi++) {
                mma16816(acc[mi][ni2 * 2 + 0], acur[mi], bf[ni2][0], bf[ni2][2]);
                mma16816(acc[mi][ni2 * 2 + 1], acur[mi], bf[ni2][1], bf[ni2][3]);
            }
        #pragma unroll
        for (int mi = 0; mi < 2; mi++)
            #pragma unroll
            for (int q = 0; q < 4; q++) acur[mi][q] = anxt[mi][q];
    }

    // ---- epilogue: +pre1, relu, dot v, reduce, transposed store ----
    float* pre1s = (float*)(smem + SMEM_PRE1);
    float* vs    = (float*)(smem + SMEM_VS);
    float* ps    = (float*)(smem + SMEM_PS);       // [128][4]

    #pragma unroll
    for (int mi = 0; mi < 2; mi++) {
        #pragma unroll
        for (int p = 0; p < 2; p++) {
            int row = wm * 32 + mi * 16 + (L >> 2) + p * 8;   // 0..127
            int bb  = row & 31;
            float s = 0.f;
            #pragma unroll
            for (int ni = 0; ni < 8; ni++) {
                int n0 = wn * 64 + ni * 8 + (L & 3) * 2;
                float e0 = acc[mi][ni][p * 2 + 0] + pre1s[bb * 257 + n0];
                float e1 = acc[mi][ni][p * 2 + 1] + pre1s[bb * 257 + n0 + 1];
                s += fmaxf(e0, 0.f) * vs[n0] + fmaxf(e1, 0.f) * vs[n0 + 1];
            }
            s += __shfl_xor_sync(0xffffffffu, s, 1);
            s += __shfl_xor_sync(0xffffffffu, s, 2);
            if ((L & 3) == 0) ps[row * 4 + wn] = s;
        }
    }
    __syncthreads();
    if (tid < 128) {
        float tot = ps[tid * 4] + ps[tid * 4 + 1] + ps[tid * 4 + 2] + ps[tid * 4 + 3];
        g_scores[(size_t)(tid & 31) * TT + blockIdx.x * 4 + (tid >> 5)] = tot;
    }
}

// ---------------------------------------------------------------------------
// Kernel 3: softmax over T per batch row (float4 vectorized).
// ---------------------------------------------------------------------------
__global__ void softmax_kernel(float* __restrict__ out) {
    int b = blockIdx.x, tid = threadIdx.x;
    __shared__ float red[32];
    __shared__ float bc;
    const float4* sc4 = (const float4*)(g_scores + (size_t)b * TT);

    float4 x = sc4[tid];
    float m = fmaxf(fmaxf(x.x, x.y), fmaxf(x.z, x.w));
    #pragma unroll
    for (int o = 16; o; o >>= 1) m = fmaxf(m, __shfl_xor_sync(0xffffffffu, m, o));
    if ((tid & 31) == 0) red[tid >> 5] = m;
    __syncthreads();
    if (tid < 32) {
        float t = red[tid];
        #pragma unroll
        for (int o = 16; o; o >>= 1) t = fmaxf(t, __shfl_xor_sync(0xffffffffu, t, o));
        if (tid == 0) bc = t;
    }
    __syncthreads();
    m = bc;
    float e0 = expf(x.x - m), e1 = expf(x.y - m), e2 = expf(x.z - m), e3 = expf(x.w - m);
    float ssum = (e0 + e1) + (e2 + e3);
    #pragma unroll
    for (int o = 16; o; o >>= 1) ssum += __shfl_xor_sync(0xffffffffu, ssum, o);
    if ((tid & 31) == 0) red[tid >> 5] = ssum;
    __syncthreads();
    if (tid < 32) {
        float t = red[tid];
        #pragma unroll
        for (int o = 16; o; o >>= 1) t += __shfl_xor_sync(0xffffffffu, t, o);
        if (tid == 0) bc = 1.f / t;
    }
    __syncthreads();
    float inv = bc;
    float4* ob4 = (float4*)(out + (size_t)b * TT);
    ob4[tid] = make_float4(e0 * inv, e1 * inv, e2 * inv, e3 * inv);
}

// ---------------------------------------------------------------------------
extern "C" void kernel_launch(void* const* d_in, const int* in_sizes, int n_in,
                              void* d_out, int out_size) {
    const float* hidden = (const float*)d_in[0];   // [B, H]
    const float* enc    = (const float*)d_in[1];   // [T, B, H]
    const float* attn_w = (const float*)d_in[2];   // [H, 2H]
    const float* attn_b = (const float*)d_in[3];   // [H]
    const float* v      = (const float*)d_in[4];   // [H]
    float* out = (float*)d_out;                    // [B, 1, T]

    cudaFuncSetAttribute(energy_kernel,
                         cudaFuncAttributeMaxDynamicSharedMemorySize, SMEM_DYN);

    init_kernel<<<1280, 256>>>(hidden, attn_w, attn_b);
    energy_kernel<<<TB / 128, 512, SMEM_DYN>>>(enc, v);
    softmax_kernel<<<BATCH, 1024>>>(out);
}

// round 9
// speedup vs baseline: 1.3617x; 1.3617x over previous
#include <cuda_runtime.h>
#include <cuda_fp16.h>
#include <cstdint>

// Problem constants
#define BATCH 32
#define TT    4096
#define HH    256
#define TB    (TT * BATCH)     // 131072 rows of enc
#define NTILES 1024            // tiles of 128 rows
#define NPERS  148             // persistent CTAs (1 per SM)

// -------------------- scratch (static device arrays) -----------------------
__device__ float g_pre1[BATCH * HH];            // W1*hidden + bias
__device__ float g_scores[BATCH * TT];          // transposed scores [b][t]
// Pre-swizzled full B tile fp16: [256 n][512B row], 16B-unit XOR swizzle
__device__ unsigned char g_bpk[131072];

// -------------------- helpers ----------------------------------------------
__device__ __forceinline__ uint32_t smem_u32(const void* p) {
    uint32_t a;
    asm("{ .reg .u64 t; cvta.to.shared.u64 t, %1; cvt.u32.u64 %0, t; }" : "=r"(a) : "l"(p));
    return a;
}
__device__ __forceinline__ void cp16(void* smem_dst, const void* gsrc) {
    unsigned s = (unsigned)__cvta_generic_to_shared(smem_dst);
    asm volatile("cp.async.cg.shared.global [%0], [%1], 16;\n" :: "r"(s), "l"(gsrc));
}
#define CP_COMMIT() asm volatile("cp.async.commit_group;\n" ::: "memory")
#define CP_WAIT0()  asm volatile("cp.async.wait_group 0;\n" ::: "memory")

__device__ __forceinline__ uint32_t pack_f16x2(float x, float y) {
    uint32_t r;
    asm("cvt.rn.f16x2.f32 %0, %1, %2;" : "=r"(r) : "f"(y), "f"(x));
    return r;
}
__device__ __forceinline__ void ldsm4(uint32_t* r, uint32_t addr) {
    asm volatile("ldmatrix.sync.aligned.m8n8.x4.shared.b16 {%0,%1,%2,%3}, [%4];"
                 : "=r"(r[0]), "=r"(r[1]), "=r"(r[2]), "=r"(r[3]) : "r"(addr));
}
__device__ __forceinline__ void mma16816(float* c, const uint32_t* a, uint32_t b0, uint32_t b1) {
    asm volatile("mma.sync.aligned.m16n8k16.row.col.f32.f16.f16.f32 "
                 "{%0,%1,%2,%3}, {%4,%5,%6,%7}, {%8,%9}, {%0,%1,%2,%3};"
                 : "+f"(c[0]), "+f"(c[1]), "+f"(c[2]), "+f"(c[3])
                 : "r"(a[0]), "r"(a[1]), "r"(a[2]), "r"(a[3]), "r"(b0), "r"(b1));
}

// ---------------------------------------------------------------------------
// Kernel 1 (fused init): blocks [0,1024) pre1, [1024,1280) bpack (full K).
// ---------------------------------------------------------------------------
__global__ void init_kernel(const float* __restrict__ hidden,
                            const float* __restrict__ attn_w,
                            const float* __restrict__ attn_b) {
    if (blockIdx.x < 1024) {
        int gw   = (blockIdx.x * 256 + threadIdx.x) >> 5;   // 0..8191
        int lane = threadIdx.x & 31;
        int b = gw >> 8, h = gw & 255;
        const float4* hp = (const float4*)(hidden + (size_t)b * HH);
        const float4* wp = (const float4*)(attn_w + (size_t)h * (2 * HH));
        float4 x0 = hp[lane],      w0 = wp[lane];
        float4 x1 = hp[lane + 32], w1 = wp[lane + 32];
        float s = x0.x*w0.x + x0.y*w0.y + x0.z*w0.z + x0.w*w0.w
                + x1.x*w1.x + x1.y*w1.y + x1.z*w1.z + x1.w*w1.w;
        #pragma unroll
        for (int o = 16; o; o >>= 1) s += __shfl_xor_sync(0xffffffffu, s, o);
        if (lane == 0) g_pre1[gw] = s + attn_b[h];
    } else {
        int idx = (blockIdx.x - 1024) * 256 + threadIdx.x;  // 0..65535
        int n = idx >> 8;
        int k = idx & 255;
        float val = attn_w[(size_t)n * 512 + 256 + k];
        __half hv = __float2half_rn(val);
        uint32_t so = (uint32_t)n * 512 + (((uint32_t)k * 2) ^ ((uint32_t)(n & 7) * 16));
        *(uint16_t*)(g_bpk + so) = __half_as_ushort(hv);
    }
}

// ---------------------------------------------------------------------------
// Kernel 2: persistent fp16 HMMA GEMM. B resident (128KB), warp tile 64x64.
// 148 CTAs x 256 thr (8 warps: wm 0..1 x wn 0..3). Tile = 128 rows x 256 cols.
// A: staged fp32->fp16, double buffer 2x16KB (K chunks of 64), pipelined
//    across tiles. Epilogue fused per tile.
// SMEM: B      @ 0        131072
//       A      @ 131072    32768  (2 x 16384)
//       pre1s  @ 163840    32896  ([32][257])
//       vs     @ 196736     1024
//       ps     @ 197760     2048  ([128][4])
// ---------------------------------------------------------------------------
#define SMEM_A    131072
#define SMEM_PRE1 163840
#define SMEM_VS   196736
#define SMEM_PS   197760
#define SMEM_DYN  199808

__global__ __launch_bounds__(256, 1)
void energy_kernel(const float* __restrict__ enc, const float* __restrict__ v) {
    extern __shared__ __align__(1024) unsigned char smem[];
    const uint32_t sb = smem_u32(smem);
    const int tid = threadIdx.x, wid = tid >> 5, L = tid & 31;
    const int wm = wid >> 2, wn = wid & 3;          // wm 0..1, wn 0..3

    // ---- one-time prologue: B (128KB cp.async), pre1s, vs ----
    #pragma unroll
    for (int st = 0; st < 32; st++) {
        int off = (tid + st * 256) * 16;
        cp16(smem + off, g_bpk + off);
    }
    CP_COMMIT();
    float* pre1s = (float*)(smem + SMEM_PRE1);
    #pragma unroll
    for (int i = 0; i < 32; i++) {
        int idx = tid + i * 256;                    // 0..8191
        pre1s[(idx >> 8) * 257 + (idx & 255)] = g_pre1[idx];
    }
    ((float*)(smem + SMEM_VS))[tid] = v[tid];

    // ---- ldsm address components ----
    const int lrow16 = L & 15;
    const uint32_t lcol = (uint32_t)(L >> 4) * 16;
    const uint32_t sw   = (uint32_t)(lrow16 & 7) * 16;
    uint32_t bRow[4], aRow[4];
    #pragma unroll
    for (int nj2 = 0; nj2 < 4; nj2++)
        bRow[nj2] = sb + (uint32_t)(wn * 64 + nj2 * 16 + lrow16) * 512;
    #pragma unroll
    for (int mi = 0; mi < 4; mi++)
        aRow[mi] = (uint32_t)(wm * 64 + mi * 16 + lrow16) * 128;

    // ---- A staging: unit u = tid + (h*2+it)*256; row=u>>3, u8=u&7 ----
    float4 stage[4];                                // 16 floats, reused per half
    auto ldg_half = [&](int t, int c, int h) {
        #pragma unroll
        for (int it = 0; it < 2; it++) {
            int u = tid + (h * 2 + it) * 256;       // 0..1023
            int row = u >> 3, u8 = u & 7;
            const float4* p = (const float4*)(enc + (size_t)(t * 128 + row) * HH + c * 64 + u8 * 8);
            stage[it * 2 + 0] = p[0];
            stage[it * 2 + 1] = p[1];
        }
    };
    auto sts_half = [&](int buf, int h) {
        #pragma unroll
        for (int it = 0; it < 2; it++) {
            int u = tid + (h * 2 + it) * 256;
            int row = u >> 3, u8 = u & 7;
            float4 a0 = stage[it * 2 + 0], a1 = stage[it * 2 + 1];
            uint4 hv = make_uint4(pack_f16x2(a0.x, a0.y), pack_f16x2(a0.z, a0.w),
                                  pack_f16x2(a1.x, a1.y), pack_f16x2(a1.z, a1.w));
            uint32_t off = (uint32_t)row * 128 + (((uint32_t)u8 * 16) ^ ((uint32_t)(row & 7) * 16));
            *(uint4*)(smem + SMEM_A + buf * 16384 + off) = hv;
        }
    };

    float acc[4][8][4];

    auto mma_ks = [&](int ksg, uint32_t abase) {
        const uint32_t koffB = (lcol | ((uint32_t)ksg * 32)) ^ sw;
        const uint32_t koffA = (lcol | ((uint32_t)(ksg & 3) * 32)) ^ sw;
        uint32_t ah[4][4];
        #pragma unroll
        for (int mi = 0; mi < 4; mi++) ldsm4(ah[mi], abase + aRow[mi] + koffA);
        uint32_t bf0[4], bf1[4];
        ldsm4(bf0, bRow[0] + koffB);
        ldsm4(bf1, bRow[1] + koffB);
        #pragma unroll
        for (int mi = 0; mi < 4; mi++) {
            mma16816(acc[mi][0], ah[mi], bf0[0], bf0[2]);
            mma16816(acc[mi][1], ah[mi], bf0[1], bf0[3]);
        }
        ldsm4(bf0, bRow[2] + koffB);
        #pragma unroll
        for (int mi = 0; mi < 4; mi++) {
            mma16816(acc[mi][2], ah[mi], bf1[0], bf1[2]);
            mma16816(acc[mi][3], ah[mi], bf1[1], bf1[3]);
        }
        ldsm4(bf1, bRow[3] + koffB);
        #pragma unroll
        for (int mi = 0; mi < 4; mi++) {
            mma16816(acc[mi][4], ah[mi], bf0[0], bf0[2]);
            mma16816(acc[mi][5], ah[mi], bf0[1], bf0[3]);
        }
        #pragma unroll
        for (int mi = 0; mi < 4; mi++) {
            mma16816(acc[mi][6], ah[mi], bf1[0], bf1[2]);
            mma16816(acc[mi][7], ah[mi], bf1[1], bf1[3]);
        }
    };

    // ---- prologue A: chunk 0 of first tile ----
    int t = blockIdx.x;
    ldg_half(t, 0, 0); sts_half(0, 0);
    ldg_half(t, 0, 1); sts_half(0, 1);
    CP_WAIT0();
    __syncthreads();

    int buf = 0;
    float* vs = (float*)(smem + SMEM_VS);
    float* ps = (float*)(smem + SMEM_PS);

    while (true) {
        #pragma unroll
        for (int mi = 0; mi < 4; mi++)
            #pragma unroll
            for (int j = 0; j < 8; j++)
                #pragma unroll
                for (int q = 0; q < 4; q++) acc[mi][j][q] = 0.f;

        #pragma unroll
        for (int c = 0; c < 4; c++) {
            const uint32_t abase = sb + SMEM_A + (uint32_t)buf * 16384;
            const int nt = (c == 3) ? t + NPERS : t;
            const int nc = (c == 3) ? 0 : c + 1;
            const bool pf = (nt < NTILES);
            if (pf) ldg_half(nt, nc, 0);
            mma_ks(c * 4 + 0, abase);
            mma_ks(c * 4 + 1, abase);
            if (pf) { sts_half(buf ^ 1, 0); ldg_half(nt, nc, 1); }
            mma_ks(c * 4 + 2, abase);
            mma_ks(c * 4 + 3, abase);
            if (pf) sts_half(buf ^ 1, 1);
            __syncthreads();
            buf ^= 1;
        }

        // ---- epilogue: +pre1, relu, dot v, reduce, transposed store ----
        #pragma unroll
        for (int mi = 0; mi < 4; mi++) {
            #pragma unroll
            for (int p = 0; p < 2; p++) {
                int row = wm * 64 + mi * 16 + (L >> 2) + p * 8;   // 0..127
                int bb  = row & 31;
                float s = 0.f;
                #pragma unroll
                for (int nj = 0; nj < 8; nj++) {
                    int n0 = wn * 64 + nj * 8 + (L & 3) * 2;
                    float e0 = acc[mi][nj][p * 2 + 0] + pre1s[bb * 257 + n0];
                    float e1 = acc[mi][nj][p * 2 + 1] + pre1s[bb * 257 + n0 + 1];
                    s += fmaxf(e0, 0.f) * vs[n0] + fmaxf(e1, 0.f) * vs[n0 + 1];
                }
                s += __shfl_xor_sync(0xffffffffu, s, 1);
                s += __shfl_xor_sync(0xffffffffu, s, 2);
                if ((L & 3) == 0) ps[row * 4 + wn] = s;
            }
        }
        __syncthreads();
        if (tid < 128) {
            float tot = ps[tid * 4] + ps[tid * 4 + 1] + ps[tid * 4 + 2] + ps[tid * 4 + 3];
            g_scores[(size_t)(tid & 31) * TT + t * 4 + (tid >> 5)] = tot;
        }

        t += NPERS;
        if (t >= NTILES) break;
    }
}

// ---------------------------------------------------------------------------
// Kernel 3: softmax over T per batch row (float4 vectorized).
// ---------------------------------------------------------------------------
__global__ void softmax_kernel(float* __restrict__ out) {
    int b = blockIdx.x, tid = threadIdx.x;
    __shared__ float red[32];
    __shared__ float bc;
    const float4* sc4 = (const float4*)(g_scores + (size_t)b * TT);

    float4 x = sc4[tid];
    float m = fmaxf(fmaxf(x.x, x.y), fmaxf(x.z, x.w));
    #pragma unroll
    for (int o = 16; o; o >>= 1) m = fmaxf(m, __shfl_xor_sync(0xffffffffu, m, o));
    if ((tid & 31) == 0) red[tid >> 5] = m;
    __syncthreads();
    if (tid < 32) {
        float t = red[tid];
        #pragma unroll
        for (int o = 16; o; o >>= 1) t = fmaxf(t, __shfl_xor_sync(0xffffffffu, t, o));
        if (tid == 0) bc = t;
    }
    __syncthreads();
    m = bc;
    float e0 = expf(x.x - m), e1 = expf(x.y - m), e2 = expf(x.z - m), e3 = expf(x.w - m);
    float ssum = (e0 + e1) + (e2 + e3);
    #pragma unroll
    for (int o = 16; o; o >>= 1) ssum += __shfl_xor_sync(0xffffffffu, ssum, o);
    if ((tid & 31) == 0) red[tid >> 5] = ssum;
    __syncthreads();
    if (tid < 32) {
        float t = red[tid];
        #pragma unroll
        for (int o = 16; o; o >>= 1) t += __shfl_xor_sync(0xffffffffu, t, o);
        if (tid == 0) bc = 1.f / t;
    }
    __syncthreads();
    float inv = bc;
    float4* ob4 = (float4*)(out + (size_t)b * TT);
    ob4[tid] = make_float4(e0 * inv, e1 * inv, e2 * inv, e3 * inv);
}

// ---------------------------------------------------------------------------
extern "C" void kernel_launch(void* const* d_in, const int* in_sizes, int n_in,
                              void* d_out, int out_size) {
    const float* hidden = (const float*)d_in[0];   // [B, H]
    const float* enc    = (const float*)d_in[1];   // [T, B, H]
    const float* attn_w = (const float*)d_in[2];   // [H, 2H]
    const float* attn_b = (const float*)d_in[3];   // [H]
    const float* v      = (const float*)d_in[4];   // [H]
    float* out = (float*)d_out;                    // [B, 1, T]

    cudaFuncSetAttribute(energy_kernel,
                         cudaFuncAttributeMaxDynamicSharedMemorySize, SMEM_DYN);

    init_kernel<<<1280, 256>>>(hidden, attn_w, attn_b);
    energy_kernel<<<NPERS, 256, SMEM_DYN>>>(enc, v);
    softmax_kernel<<<BATCH, 1024>>>(out);
}